// round 1
// baseline (speedup 1.0000x reference)
#include <cuda_runtime.h>
#include <math.h>

// Problem constants
#define NB 2          // batch
#define NC 50         // channels
#define NCR 25        // reduced channels
#define NP 2304       // H*W = 48*48
#define STOT 7470     // total pyramid spatial positions (= L)
#define LPAD 7552     // L padded to multiple of 128
#define KQ 240        // 225 patch dims padded to multiple of 16
#define NV 512        // 450 value dims padded to multiple of 128

__constant__ int c_n[5]   = {48, 43, 38, 33, 28};
__constant__ int c_off[5] = {0, 2304, 4153, 5597, 6686};

// ---- scratch (static __device__ arrays; no allocations) ----
__device__ float g_ref [(size_t)NB * NC  * STOT];   // resized pyramid images
__device__ float g_mb  [(size_t)NB * NCR * NP];     // match_base
__device__ float g_mall[(size_t)NB * NCR * STOT];   // keys image (all scales)
__device__ float g_ball[(size_t)NB * NC  * STOT];   // values image (all scales)
__device__ float g_xq  [(size_t)NB * NP * KQ];      // query patches [B][P][240]
__device__ float g_wn  [(size_t)NB * LPAD * KQ];    // normalized key patches *10
__device__ float g_raw [(size_t)NB * LPAD * NV];    // value patches [B][Lp][512]
__device__ float g_sc  [(size_t)NB * NP * LPAD];    // scores / attn [B][P][Lp]
__device__ float g_O   [(size_t)NB * NP * NV];      // attn-weighted values

// ---------------------------------------------------------------------------
// conv1x1 + PReLU : out[b][oc][sp] = prelu(sum_c W[oc][c]*in[b][c][sp] + bias)
// grid.y = b*Cout+oc, grid.x covers S
__global__ void k_conv1x1(const float* __restrict__ in, const float* __restrict__ Wt,
                          const float* __restrict__ bias, const float* __restrict__ slope,
                          float* __restrict__ out, int Cout, int S)
{
    __shared__ float w[NC];
    __shared__ float sb[2];
    int bo = blockIdx.y;
    int b  = bo / Cout;
    int oc = bo % Cout;
    if (threadIdx.x < NC) w[threadIdx.x] = Wt[oc * NC + threadIdx.x];
    if (threadIdx.x == 0) { sb[0] = bias[oc]; sb[1] = slope[0]; }
    __syncthreads();
    int sp = blockIdx.x * blockDim.x + threadIdx.x;
    if (sp >= S) return;
    const float* ip = in + (size_t)b * NC * S + sp;
    float acc = sb[0];
#pragma unroll
    for (int c = 0; c < NC; c++) acc = fmaf(w[c], ip[(size_t)c * S], acc);
    out[(size_t)bo * S + sp] = acc >= 0.f ? acc : sb[1] * acc;
}

// ---------------------------------------------------------------------------
// bicubic resize (align_corners=True, Keys a=-0.75, border clamp), separable
// weights composed into 4x4 product taps. blockIdx.z = scale, blockIdx.y = b*C+c
__device__ __forceinline__ float cubw(float t)
{
    float at = fabsf(t);
    float w1 = (1.25f * at - 2.25f) * at * at + 1.f;
    float w2 = -0.75f * (((at - 5.f) * at + 8.f) * at - 4.f);
    return at <= 1.f ? w1 : (at < 2.f ? w2 : 0.f);
}

__global__ void k_resize(const float* __restrict__ x)
{
    int s = blockIdx.z;
    int n = c_n[s];
    int idx = blockIdx.x * blockDim.x + threadIdx.x;
    if (idx >= n * n) return;
    int bc = blockIdx.y;
    int oy = idx / n, ox = idx % n;
    float scale = (float)(47.0 / (double)(n - 1));
    float syf = (float)oy * scale, sxf = (float)ox * scale;
    float fy0 = floorf(syf), fx0 = floorf(sxf);
    float fy = syf - fy0, fx = sxf - fx0;
    int iy0 = (int)fy0, ix0 = (int)fx0;
    float wy[4], wx[4];
    int iy[4], ix[4];
#pragma unroll
    for (int d = 0; d < 4; d++) {
        wy[d] = cubw(fy - (float)(d - 1));
        wx[d] = cubw(fx - (float)(d - 1));
        int a1 = iy0 + d - 1; iy[d] = a1 < 0 ? 0 : (a1 > 47 ? 47 : a1);
        int a2 = ix0 + d - 1; ix[d] = a2 < 0 ? 0 : (a2 > 47 ? 47 : a2);
    }
    const float* xp = x + (size_t)bc * NP;
    float acc = 0.f;
#pragma unroll
    for (int u = 0; u < 4; u++) {
        float r = 0.f;
#pragma unroll
        for (int v = 0; v < 4; v++) r = fmaf(wx[v], xp[iy[u] * 48 + ix[v]], r);
        acc = fmaf(wy[u], r, acc);
    }
    g_ref[(size_t)bc * STOT + c_off[s] + idx] = acc;
}

// ---------------------------------------------------------------------------
// query patches: g_xq[b][p][k] = match_base patch (zero pad), k<225; pad->0
__global__ void k_xq()
{
    int idx = blockIdx.x * blockDim.x + threadIdx.x;
    if (idx >= NB * NP * KQ) return;
    int k = idx % KQ;
    int p = (idx / KQ) % NP;
    int b = idx / (KQ * NP);
    float v = 0.f;
    if (k < 225) {
        int c = k / 9, t = k % 9, di = t / 3, dj = t % 3;
        int y = p / 48, xx = p % 48;
        int sy = y + di - 1, sx = xx + dj - 1;
        if (sy >= 0 && sy < 48 && sx >= 0 && sx < 48)
            v = g_mb[((size_t)b * NCR + c) * NP + sy * 48 + sx];
    }
    g_xq[idx] = v;
}

__device__ __forceinline__ int scale_of(int l)
{
    int s = 4;
    while (s > 0 && l < c_off[s]) s--;
    return s;
}

// normalized key patches (fold softmax scale 10 into rows). one warp per row.
__global__ void k_wn()
{
    int warp = (blockIdx.x * blockDim.x + threadIdx.x) >> 5;
    int lane = threadIdx.x & 31;
    if (warp >= NB * LPAD) return;
    int b = warp / LPAD;
    int l = warp % LPAD;
    float* rowp = g_wn + ((size_t)b * LPAD + l) * KQ;
    if (l >= STOT) {
        for (int k = lane; k < KQ; k += 32) rowp[k] = 0.f;
        return;
    }
    int s = scale_of(l);
    int n = c_n[s];
    int ll = l - c_off[s];
    int y = ll / n, xx = ll % n;
    float vals[8];
    float ss = 0.f;
    int i = 0;
    for (int k = lane; k < KQ; k += 32, i++) {
        float v = 0.f;
        if (k < 225) {
            int c = k / 9, t = k % 9, di = t / 3, dj = t % 3;
            int sy = y + di - 1, sx = xx + dj - 1;
            if (sy >= 0 && sy < n && sx >= 0 && sx < n)
                v = g_mall[((size_t)b * NCR + c) * STOT + c_off[s] + sy * n + sx];
        }
        vals[i] = v;
        ss = fmaf(v, v, ss);
    }
#pragma unroll
    for (int o = 16; o; o >>= 1) ss += __shfl_xor_sync(0xffffffffu, ss, o);
    float nrm = sqrtf(ss);
    float sc = 10.f / fmaxf(nrm, 1e-4f);
    i = 0;
    for (int k = lane; k < KQ; k += 32, i++) rowp[k] = vals[i] * sc;
}

// value patches: g_raw[b][l][k], k<450 real, padded rows/cols -> 0
__global__ void k_raw()
{
    int idx = blockIdx.x * blockDim.x + threadIdx.x;
    if (idx >= NB * LPAD * NV) return;
    int k = idx % NV;
    int l = (idx / NV) % LPAD;
    int b = idx / (NV * LPAD);
    float v = 0.f;
    if (l < STOT && k < 450) {
        int s = scale_of(l);
        int n = c_n[s];
        int ll = l - c_off[s];
        int y = ll / n, xx = ll % n;
        int c = k / 9, t = k % 9, di = t / 3, dj = t % 3;
        int sy = y + di - 1, sx = xx + dj - 1;
        if (sy >= 0 && sy < n && sx >= 0 && sx < n)
            v = g_ball[((size_t)b * NC + c) * STOT + c_off[s] + sy * n + sx];
    }
    g_raw[idx] = v;
}

// ---------------------------------------------------------------------------
// fp32 GEMM, 128x128 tiles, BK=16, 8x8 per thread, no predication (padded dims)
// C[M,N] = A[M,K] * (BT ? B[N,K]^T : B[K,N])
template <bool BT>
__global__ void __launch_bounds__(256, 2)
k_gemm(const float* __restrict__ A, const float* __restrict__ Bm, float* __restrict__ Cm,
       int Kdim, int lda, int ldb, int ldc, size_t sA, size_t sB, size_t sC)
{
    __shared__ __align__(16) float As[16][128];
    __shared__ __align__(16) float Bs[16][128];
    const float* Ab = A + blockIdx.z * sA;
    const float* Bb = Bm + blockIdx.z * sB;
    float* Cb = Cm + blockIdx.z * sC;
    const int m0 = blockIdx.y * 128, n0 = blockIdx.x * 128;
    const int t = threadIdx.x;
    const int tx = t & 15, ty = t >> 4;
    float acc[8][8];
#pragma unroll
    for (int i = 0; i < 8; i++)
#pragma unroll
        for (int j = 0; j < 8; j++) acc[i][j] = 0.f;

    for (int k0 = 0; k0 < Kdim; k0 += 16) {
#pragma unroll
        for (int rep = 0; rep < 2; rep++) {
            int q = t + rep * 256;
            int row = q >> 2, kq = (q & 3) << 2;
            float4 v = *(const float4*)(Ab + (size_t)(m0 + row) * lda + (k0 + kq));
            As[kq + 0][row] = v.x; As[kq + 1][row] = v.y;
            As[kq + 2][row] = v.z; As[kq + 3][row] = v.w;
        }
        if (BT) {
#pragma unroll
            for (int rep = 0; rep < 2; rep++) {
                int q = t + rep * 256;
                int row = q >> 2, kq = (q & 3) << 2;
                float4 v = *(const float4*)(Bb + (size_t)(n0 + row) * ldb + (k0 + kq));
                Bs[kq + 0][row] = v.x; Bs[kq + 1][row] = v.y;
                Bs[kq + 2][row] = v.z; Bs[kq + 3][row] = v.w;
            }
        } else {
#pragma unroll
            for (int rep = 0; rep < 2; rep++) {
                int q = t + rep * 256;
                int kr = q >> 5, c4 = (q & 31) << 2;
                *(float4*)&Bs[kr][c4] =
                    *(const float4*)(Bb + (size_t)(k0 + kr) * ldb + (n0 + c4));
            }
        }
        __syncthreads();
#pragma unroll
        for (int kk = 0; kk < 16; kk++) {
            float ra[8], rb[8];
            *(float4*)(ra)     = *(const float4*)&As[kk][ty * 8];
            *(float4*)(ra + 4) = *(const float4*)&As[kk][ty * 8 + 4];
            *(float4*)(rb)     = *(const float4*)&Bs[kk][tx * 8];
            *(float4*)(rb + 4) = *(const float4*)&Bs[kk][tx * 8 + 4];
#pragma unroll
            for (int i = 0; i < 8; i++)
#pragma unroll
                for (int j = 0; j < 8; j++)
                    acc[i][j] = fmaf(ra[i], rb[j], acc[i][j]);
        }
        __syncthreads();
    }
#pragma unroll
    for (int i = 0; i < 8; i++) {
        float* cp = Cb + (size_t)(m0 + ty * 8 + i) * ldc + (n0 + tx * 8);
        float4 v0 = make_float4(acc[i][0], acc[i][1], acc[i][2], acc[i][3]);
        float4 v1 = make_float4(acc[i][4], acc[i][5], acc[i][6], acc[i][7]);
        *(float4*)cp = v0;
        *(float4*)(cp + 4) = v1;
    }
}

// ---------------------------------------------------------------------------
// softmax over L for each (b,p) row of g_sc (contiguous rows). warp per row.
__global__ void k_softmax()
{
    int warp = (blockIdx.x * blockDim.x + threadIdx.x) >> 5;
    int lane = threadIdx.x & 31;
    if (warp >= NB * NP) return;
    float* row = g_sc + (size_t)warp * LPAD;
    float m = -1e30f, sum = 0.f;
    for (int l = lane; l < STOT; l += 32) {
        float v = row[l];
        float nm = fmaxf(m, v);
        sum = sum * __expf(m - nm) + __expf(v - nm);
        m = nm;
    }
#pragma unroll
    for (int o = 16; o; o >>= 1) {
        float mo = __shfl_xor_sync(0xffffffffu, m, o);
        float so = __shfl_xor_sync(0xffffffffu, sum, o);
        float nm = fmaxf(m, mo);
        sum = sum * __expf(m - nm) + so * __expf(mo - nm);
        m = nm;
    }
    float inv = 1.f / sum;
    for (int l = lane; l < LPAD; l += 32)
        row[l] = (l < STOT) ? __expf(row[l] - m) * inv : 0.f;
}

// ---------------------------------------------------------------------------
// epilogue: transposed-conv combine of O + residual
// out[b][c][i][j] = x + 0.25 * sum_{u,v} O[b][(i-u+1)*48+(j-v+1)][c*9+u*3+v]
__global__ void k_epi(const float* __restrict__ x, float* __restrict__ out)
{
    int idx = blockIdx.x * blockDim.x + threadIdx.x;
    if (idx >= NB * NC * NP) return;
    int p = idx % NP;
    int c = (idx / NP) % NC;
    int b = idx / (NP * NC);
    int i = p / 48, j = p % 48;
    float acc = 0.f;
#pragma unroll
    for (int u = 0; u < 3; u++)
#pragma unroll
        for (int v = 0; v < 3; v++) {
            int y = i - u + 1, xx = j - v + 1;
            if (y >= 0 && y < 48 && xx >= 0 && xx < 48)
                acc += g_O[((size_t)b * NP + y * 48 + xx) * NV + c * 9 + u * 3 + v];
        }
    out[idx] = x[idx] + 0.25f * acc;
}

// ---------------------------------------------------------------------------
extern "C" void kernel_launch(void* const* d_in, const int* in_sizes, int n_in,
                              void* d_out, int out_size)
{
    const float* x    = (const float*)d_in[0];
    const float* W_mb = (const float*)d_in[1];
    const float* b_mb = (const float*)d_in[2];
    const float* a_mb = (const float*)d_in[3];
    const float* W_m  = (const float*)d_in[4];
    const float* b_m  = (const float*)d_in[5];
    const float* a_m  = (const float*)d_in[6];
    const float* W_a  = (const float*)d_in[7];
    const float* b_a  = (const float*)d_in[8];
    const float* a_a  = (const float*)d_in[9];
    float* out = (float*)d_out;

    float* p_mb;   cudaGetSymbolAddress((void**)&p_mb, g_mb);
    float* p_ref;  cudaGetSymbolAddress((void**)&p_ref, g_ref);
    float* p_mall; cudaGetSymbolAddress((void**)&p_mall, g_mall);
    float* p_ball; cudaGetSymbolAddress((void**)&p_ball, g_ball);
    float* p_xq;   cudaGetSymbolAddress((void**)&p_xq, g_xq);
    float* p_wn;   cudaGetSymbolAddress((void**)&p_wn, g_wn);
    float* p_raw;  cudaGetSymbolAddress((void**)&p_raw, g_raw);
    float* p_sc;   cudaGetSymbolAddress((void**)&p_sc, g_sc);
    float* p_O;    cudaGetSymbolAddress((void**)&p_O, g_O);

    // 1) match_base = prelu(conv1x1(x, W_mb))
    k_conv1x1<<<dim3(9, NB * NCR), 256>>>(x, W_mb, b_mb, a_mb, p_mb, NCR, NP);
    // 2) pyramid bicubic resize of x into g_ref (scale 0 is exact copy)
    k_resize<<<dim3(9, NB * NC, 5), 256>>>(x);
    // 3) keys / values images over all pyramid levels
    k_conv1x1<<<dim3(30, NB * NCR), 256>>>(p_ref, W_m, b_m, a_m, p_mall, NCR, STOT);
    k_conv1x1<<<dim3(30, NB * NC), 256>>>(p_ref, W_a, b_a, a_a, p_ball, NC, STOT);
    // 4) patch gathers
    k_xq<<<(NB * NP * KQ + 255) / 256, 256>>>();
    k_wn<<<(NB * LPAD * 32 + 255) / 256, 256>>>();
    k_raw<<<(NB * LPAD * NV + 255) / 256, 256>>>();
    // 5) scores = xq @ wn^T  (10x folded into wn)   [P x Lp]
    k_gemm<true><<<dim3(LPAD / 128, NP / 128, NB), 256>>>(
        p_xq, p_wn, p_sc, KQ, KQ, KQ, LPAD,
        (size_t)NP * KQ, (size_t)LPAD * KQ, (size_t)NP * LPAD);
    // 6) softmax over L per (b,p) row
    k_softmax<<<(NB * NP * 32 + 255) / 256, 256>>>();
    // 7) O = attn @ raw   [P x 512]
    k_gemm<false><<<dim3(NV / 128, NP / 128, NB), 256>>>(
        p_sc, p_raw, p_O, LPAD, LPAD, NV, NV,
        (size_t)NP * LPAD, (size_t)LPAD * NV, (size_t)NP * NV);
    // 8) transposed-conv combine + residual
    k_epi<<<(NB * NC * NP + 255) / 256, 256>>>(x, out);
}

// round 4
// speedup vs baseline: 2.2898x; 2.2898x over previous
#include <cuda_runtime.h>
#include <cuda_bf16.h>
#include <math.h>
#include <stdint.h>

// Problem constants
#define NB 2          // batch
#define NC 50         // channels
#define NCR 25        // reduced channels
#define NP 2304       // H*W = 48*48
#define STOT 7470     // total pyramid spatial positions (= L)
#define LPAD 7552     // L padded to multiple of 128
#define KQ 240        // 225 patch dims padded to 240 (fp32 stage)
#define KS1 256       // per-section K for GEMM1 (bf16 split)
#define KP1 768       // 3*256, GEMM1 split-K total
#define KP2 22656     // 3*7552, GEMM2 split-K total
#define NV 512        // 450 value dims padded to 512

__constant__ int c_n[5]   = {48, 43, 38, 33, 28};
__constant__ int c_off[5] = {0, 2304, 4153, 5597, 6686};

// ---- scratch (static __device__ arrays; no allocations) ----
__device__ float g_ref [(size_t)NB * NC  * STOT];
__device__ float g_mb  [(size_t)NB * NCR * NP];
__device__ float g_mall[(size_t)NB * NCR * STOT];
__device__ float g_ball[(size_t)NB * NC  * STOT];
__device__ float g_xq  [(size_t)NB * NP * KQ];
__device__ float g_wn  [(size_t)NB * LPAD * KQ];
__device__ float g_sc  [(size_t)NB * NP * LPAD];          // scores (pre-softmax)
__device__ float g_O   [(size_t)NB * NP * NV];            // attn @ values
__device__ __align__(256) __nv_bfloat16 g_xqs  [(size_t)NB * NP * KP1];   // A1 (hi,lo,hi)
__device__ __align__(256) __nv_bfloat16 g_wns  [(size_t)NB * LPAD * KP1]; // B1 (hi,hi,lo)
__device__ __align__(256) __nv_bfloat16 g_attns[(size_t)NB * NP * KP2];   // A2 (hi,lo,hi)
__device__ __align__(256) __nv_bfloat16 g_rawTs[(size_t)NB * NV * KP2];   // B2 (hi,hi,lo)

// ===========================================================================
// PTX helpers
// ===========================================================================
__device__ __forceinline__ uint32_t smem_u32(const void* p)
{
    uint32_t a;
    asm("{ .reg .u64 t; cvta.to.shared.u64 t, %1; cvt.u32.u64 %0, t; }" : "=r"(a) : "l"(p));
    return a;
}
__device__ __forceinline__ void cpa16(uint32_t dst, const void* src)
{
    asm volatile("cp.async.cg.shared.global [%0], [%1], 16;" :: "r"(dst), "l"(src));
}
__device__ __forceinline__ void cpa_commit() { asm volatile("cp.async.commit_group;" ::: "memory"); }
template <int N> __device__ __forceinline__ void cpa_wait()
{
    asm volatile("cp.async.wait_group %0;" :: "n"(N) : "memory");
}
__device__ __forceinline__ void ldm_x4(uint32_t& r0, uint32_t& r1, uint32_t& r2, uint32_t& r3,
                                       uint32_t addr)
{
    asm volatile("ldmatrix.sync.aligned.m8n8.x4.shared.b16 {%0,%1,%2,%3}, [%4];"
                 : "=r"(r0), "=r"(r1), "=r"(r2), "=r"(r3) : "r"(addr));
}
__device__ __forceinline__ void mma16816(float* d, const uint32_t* a, const uint32_t* b)
{
    asm volatile("mma.sync.aligned.m16n8k16.row.col.f32.bf16.bf16.f32 "
                 "{%0,%1,%2,%3}, {%4,%5,%6,%7}, {%8,%9}, {%0,%1,%2,%3};"
                 : "+f"(d[0]), "+f"(d[1]), "+f"(d[2]), "+f"(d[3])
                 : "r"(a[0]), "r"(a[1]), "r"(a[2]), "r"(a[3]), "r"(b[0]), "r"(b[1]));
}
__device__ __forceinline__ uint32_t swz(uint32_t off) { return off ^ ((off >> 3) & 0x70); }

// ===========================================================================
// producers (validated in round 1)
// ===========================================================================
__global__ void k_conv1x1(const float* __restrict__ in, const float* __restrict__ Wt,
                          const float* __restrict__ bias, const float* __restrict__ slope,
                          float* __restrict__ out, int Cout, int S)
{
    __shared__ float w[NC];
    __shared__ float sb[2];
    int bo = blockIdx.y;
    int b  = bo / Cout;
    int oc = bo % Cout;
    if (threadIdx.x < NC) w[threadIdx.x] = Wt[oc * NC + threadIdx.x];
    if (threadIdx.x == 0) { sb[0] = bias[oc]; sb[1] = slope[0]; }
    __syncthreads();
    int sp = blockIdx.x * blockDim.x + threadIdx.x;
    if (sp >= S) return;
    const float* ip = in + (size_t)b * NC * S + sp;
    float acc = sb[0];
#pragma unroll
    for (int c = 0; c < NC; c++) acc = fmaf(w[c], ip[(size_t)c * S], acc);
    out[(size_t)bo * S + sp] = acc >= 0.f ? acc : sb[1] * acc;
}

__device__ __forceinline__ float cubw(float t)
{
    float at = fabsf(t);
    float w1 = (1.25f * at - 2.25f) * at * at + 1.f;
    float w2 = -0.75f * (((at - 5.f) * at + 8.f) * at - 4.f);
    return at <= 1.f ? w1 : (at < 2.f ? w2 : 0.f);
}

__global__ void k_resize(const float* __restrict__ x)
{
    int s = blockIdx.z;
    int n = c_n[s];
    int idx = blockIdx.x * blockDim.x + threadIdx.x;
    if (idx >= n * n) return;
    int bc = blockIdx.y;
    int oy = idx / n, ox = idx % n;
    float scale = (float)(47.0 / (double)(n - 1));
    float syf = (float)oy * scale, sxf = (float)ox * scale;
    float fy0 = floorf(syf), fx0 = floorf(sxf);
    float fy = syf - fy0, fx = sxf - fx0;
    int iy0 = (int)fy0, ix0 = (int)fx0;
    float wy[4], wx[4];
    int iy[4], ix[4];
#pragma unroll
    for (int d = 0; d < 4; d++) {
        wy[d] = cubw(fy - (float)(d - 1));
        wx[d] = cubw(fx - (float)(d - 1));
        int a1 = iy0 + d - 1; iy[d] = a1 < 0 ? 0 : (a1 > 47 ? 47 : a1);
        int a2 = ix0 + d - 1; ix[d] = a2 < 0 ? 0 : (a2 > 47 ? 47 : a2);
    }
    const float* xp = x + (size_t)bc * NP;
    float acc = 0.f;
#pragma unroll
    for (int u = 0; u < 4; u++) {
        float r = 0.f;
#pragma unroll
        for (int v = 0; v < 4; v++) r = fmaf(wx[v], xp[iy[u] * 48 + ix[v]], r);
        acc = fmaf(wy[u], r, acc);
    }
    g_ref[(size_t)bc * STOT + c_off[s] + idx] = acc;
}

__global__ void k_xq()
{
    int idx = blockIdx.x * blockDim.x + threadIdx.x;
    if (idx >= NB * NP * KQ) return;
    int k = idx % KQ;
    int p = (idx / KQ) % NP;
    int b = idx / (KQ * NP);
    float v = 0.f;
    if (k < 225) {
        int c = k / 9, t = k % 9, di = t / 3, dj = t % 3;
        int y = p / 48, xx = p % 48;
        int sy = y + di - 1, sx = xx + dj - 1;
        if (sy >= 0 && sy < 48 && sx >= 0 && sx < 48)
            v = g_mb[((size_t)b * NCR + c) * NP + sy * 48 + sx];
    }
    g_xq[idx] = v;
}

__device__ __forceinline__ int scale_of(int l)
{
    int s = 4;
    while (s > 0 && l < c_off[s]) s--;
    return s;
}

__global__ void k_wn()
{
    int warp = (blockIdx.x * blockDim.x + threadIdx.x) >> 5;
    int lane = threadIdx.x & 31;
    if (warp >= NB * LPAD) return;
    int b = warp / LPAD;
    int l = warp % LPAD;
    float* rowp = g_wn + ((size_t)b * LPAD + l) * KQ;
    if (l >= STOT) {
        for (int k = lane; k < KQ; k += 32) rowp[k] = 0.f;
        return;
    }
    int s = scale_of(l);
    int n = c_n[s];
    int ll = l - c_off[s];
    int y = ll / n, xx = ll % n;
    float vals[8];
    float ss = 0.f;
    int i = 0;
    for (int k = lane; k < KQ; k += 32, i++) {
        float v = 0.f;
        if (k < 225) {
            int c = k / 9, t = k % 9, di = t / 3, dj = t % 3;
            int sy = y + di - 1, sx = xx + dj - 1;
            if (sy >= 0 && sy < n && sx >= 0 && sx < n)
                v = g_mall[((size_t)b * NCR + c) * STOT + c_off[s] + sy * n + sx];
        }
        vals[i] = v;
        ss = fmaf(v, v, ss);
    }
#pragma unroll
    for (int o = 16; o; o >>= 1) ss += __shfl_xor_sync(0xffffffffu, ss, o);
    float nrm = sqrtf(ss);
    float sc = 10.f / fmaxf(nrm, 1e-4f);
    i = 0;
    for (int k = lane; k < KQ; k += 32, i++) rowp[k] = vals[i] * sc;
}

// ---- bf16 split producers ----
__device__ __forceinline__ void split2(float v, __nv_bfloat16& h, __nv_bfloat16& l)
{
    h = __float2bfloat16(v);
    l = __float2bfloat16(v - __bfloat162float(h));
}

__global__ void k_split_q()
{
    int idx = blockIdx.x * blockDim.x + threadIdx.x;
    if (idx >= NB * NP * KS1) return;
    int k = idx & 255;
    int p = (idx >> 8) % NP;
    int b = idx / (KS1 * NP);
    float v = (k < KQ) ? g_xq[((size_t)b * NP + p) * KQ + k] : 0.f;
    __nv_bfloat16 h, l;
    split2(v, h, l);
    __nv_bfloat16* o = g_xqs + ((size_t)b * NP + p) * KP1;
    o[k] = h; o[KS1 + k] = l; o[2 * KS1 + k] = h;
}

__global__ void k_split_wn()
{
    int idx = blockIdx.x * blockDim.x + threadIdx.x;
    if (idx >= NB * LPAD * KS1) return;
    int k = idx & 255;
    int r = (idx >> 8) % LPAD;
    int b = idx / (KS1 * LPAD);
    float v = (k < KQ) ? g_wn[((size_t)b * LPAD + r) * KQ + k] : 0.f;
    __nv_bfloat16 h, l;
    split2(v, h, l);
    __nv_bfloat16* o = g_wns + ((size_t)b * LPAD + r) * KP1;
    o[k] = h; o[KS1 + k] = h; o[2 * KS1 + k] = l;
}

__global__ void k_rawTs()
{
    int idx = blockIdx.x * blockDim.x + threadIdx.x;
    if (idx >= NB * NV * LPAD) return;
    int l = idx % LPAD;
    int n = (idx / LPAD) % NV;
    int b = idx / (LPAD * NV);
    float v = 0.f;
    if (l < STOT && n < 450) {
        int s = scale_of(l);
        int nn = c_n[s];
        int ll = l - c_off[s];
        int y = ll / nn, xx = ll % nn;
        int c = n / 9, t = n % 9, di = t / 3, dj = t % 3;
        int sy = y + di - 1, sx = xx + dj - 1;
        if (sy >= 0 && sy < nn && sx >= 0 && sx < nn)
            v = g_ball[((size_t)b * NC + c) * STOT + c_off[s] + sy * nn + sx];
    }
    __nv_bfloat16 h, lo;
    split2(v, h, lo);
    __nv_bfloat16* o = g_rawTs + ((size_t)b * NV + n) * KP2;
    o[l] = h; o[LPAD + l] = h; o[2 * LPAD + l] = lo;
}

// softmax over L per (b,p) row + fused A-type split (hi, lo, hi)
__global__ void k_softmax_split()
{
    int warp = (blockIdx.x * blockDim.x + threadIdx.x) >> 5;
    int lane = threadIdx.x & 31;
    if (warp >= NB * NP) return;
    const float* row = g_sc + (size_t)warp * LPAD;
    float m = -1e30f, sum = 0.f;
    for (int l = lane; l < STOT; l += 32) {
        float v = row[l];
        float nm = fmaxf(m, v);
        sum = sum * __expf(m - nm) + __expf(v - nm);
        m = nm;
    }
#pragma unroll
    for (int o = 16; o; o >>= 1) {
        float mo = __shfl_xor_sync(0xffffffffu, m, o);
        float so = __shfl_xor_sync(0xffffffffu, sum, o);
        float nm = fmaxf(m, mo);
        sum = sum * __expf(m - nm) + so * __expf(mo - nm);
        m = nm;
    }
    float inv = 1.f / sum;
    __nv_bfloat16* o = g_attns + (size_t)warp * KP2;
    for (int l = lane; l < LPAD; l += 32) {
        float a = (l < STOT) ? __expf(row[l] - m) * inv : 0.f;
        __nv_bfloat16 h, lo;
        split2(a, h, lo);
        o[l] = h; o[LPAD + l] = lo; o[2 * LPAD + l] = h;
    }
}

// ===========================================================================
// bf16 HMMA GEMM: C[M,N] = A[M,K'] * B[N,K']^T (both K-major bf16)
// CTA 128x128, BK=64, 8 warps (2x4), warp tile 64x32, m16n8k16 mma
// SW128 swizzled smem, double-buffered cp.async
// ===========================================================================
__device__ __forceinline__ void load_tile(uint32_t sdst, const char* gsrc,
                                          size_t ldbytes, int tid)
{
#pragma unroll
    for (int i = 0; i < 4; i++) {        // 256 threads * 4 = 1024 chunks of 16B
        int u = tid + i * 256;
        int row = u >> 3, seg = u & 7;
        uint32_t off = swz((uint32_t)(row * 128 + seg * 16));
        cpa16(sdst + off, gsrc + (size_t)row * ldbytes + seg * 16);
    }
}

__global__ void __launch_bounds__(256)
k_mma(const __nv_bfloat16* __restrict__ A, const __nv_bfloat16* __restrict__ B,
      float* __restrict__ C, int nch, int lda, int ldb, int ldc,
      size_t sA, size_t sB, size_t sC)
{
    extern __shared__ char smem[];
    const uint32_t tile0 = (smem_u32(smem) + 1023u) & ~1023u;
    const int tid = threadIdx.x, wid = tid >> 5, lane = tid & 31;
    const int wm = wid >> 2, wn = wid & 3;       // warp grid 2x4

    const char* Abase = (const char*)(A + blockIdx.z * sA + (size_t)blockIdx.y * 128 * lda);
    const char* Bbase = (const char*)(B + blockIdx.z * sB + (size_t)blockIdx.x * 128 * ldb);
    const size_t ldab = (size_t)lda * 2, ldbb = (size_t)ldb * 2;

    float acc[4][4][4];
#pragma unroll
    for (int i = 0; i < 4; i++)
#pragma unroll
        for (int j = 0; j < 4; j++)
#pragma unroll
            for (int r = 0; r < 4; r++) acc[i][j][r] = 0.f;

    // per-lane ldmatrix row/chunk components (constant across iters)
    const int a_row = wm * 64 + (lane & 15);        // + mi*16
    const int a_chk = lane >> 4;                    // 0/1 -> k sub-chunk
    const int b_row = wn * 32 + ((lane >> 4) << 3) + (lane & 7);  // + nj16*16
    const int b_chk = (lane >> 3) & 1;

    // prologue: chunk 0 -> stage 0
    load_tile(tile0,         Abase, ldab, tid);
    load_tile(tile0 + 16384, Bbase, ldbb, tid);
    cpa_commit();

    for (int c = 0; c < nch; c++) {
        if (c + 1 < nch) {
            uint32_t t1 = tile0 + (uint32_t)((c + 1) & 1) * 32768u;
            load_tile(t1,         Abase + (size_t)(c + 1) * 128, ldab, tid);
            load_tile(t1 + 16384, Bbase + (size_t)(c + 1) * 128, ldbb, tid);
            cpa_commit();
            cpa_wait<1>();
        } else {
            cpa_wait<0>();
        }
        __syncthreads();
        uint32_t sa = tile0 + (uint32_t)(c & 1) * 32768u;
        uint32_t sb = sa + 16384;
#pragma unroll
        for (int kb = 0; kb < 4; kb++) {
            uint32_t af[4][4], bf[4][2];
#pragma unroll
            for (int mi = 0; mi < 4; mi++) {
                uint32_t off = swz((uint32_t)((a_row + mi * 16) * 128 + (kb * 2 + a_chk) * 16));
                ldm_x4(af[mi][0], af[mi][1], af[mi][2], af[mi][3], sa + off);
            }
#pragma unroll
            for (int nj = 0; nj < 2; nj++) {
                uint32_t off = swz((uint32_t)((b_row + nj * 16) * 128 + (kb * 2 + b_chk) * 16));
                uint32_t r0, r1, r2, r3;
                ldm_x4(r0, r1, r2, r3, sb + off);
                bf[nj * 2][0] = r0; bf[nj * 2][1] = r1;
                bf[nj * 2 + 1][0] = r2; bf[nj * 2 + 1][1] = r3;
            }
#pragma unroll
            for (int mi = 0; mi < 4; mi++)
#pragma unroll
                for (int nj = 0; nj < 4; nj++)
                    mma16816(acc[mi][nj], af[mi], bf[nj]);
        }
        __syncthreads();
    }

    // epilogue
    float* Cb = C + blockIdx.z * sC;
    const int m0g = blockIdx.y * 128 + wm * 64;
    const int n0g = blockIdx.x * 128 + wn * 32;
#pragma unroll
    for (int mi = 0; mi < 4; mi++)
#pragma unroll
        for (int nj = 0; nj < 4; nj++) {
            int r = m0g + mi * 16 + (lane >> 2);
            int cc = n0g + nj * 8 + (lane & 3) * 2;
            *(float2*)(Cb + (size_t)r * ldc + cc) = make_float2(acc[mi][nj][0], acc[mi][nj][1]);
            *(float2*)(Cb + (size_t)(r + 8) * ldc + cc) = make_float2(acc[mi][nj][2], acc[mi][nj][3]);
        }
}

// ---------------------------------------------------------------------------
// epilogue: transposed-conv combine of O + residual
__global__ void k_epi(const float* __restrict__ x, float* __restrict__ out)
{
    int idx = blockIdx.x * blockDim.x + threadIdx.x;
    if (idx >= NB * NC * NP) return;
    int p = idx % NP;
    int c = (idx / NP) % NC;
    int b = idx / (NP * NC);
    int i = p / 48, j = p % 48;
    float acc = 0.f;
#pragma unroll
    for (int u = 0; u < 3; u++)
#pragma unroll
        for (int v = 0; v < 3; v++) {
            int y = i - u + 1, xx = j - v + 1;
            if (y >= 0 && y < 48 && xx >= 0 && xx < 48)
                acc += g_O[((size_t)b * NP + y * 48 + xx) * NV + c * 9 + u * 3 + v];
        }
    out[idx] = x[idx] + 0.25f * acc;
}

// ---------------------------------------------------------------------------
#define MMA_SMEM (65536 + 1024)

extern "C" void kernel_launch(void* const* d_in, const int* in_sizes, int n_in,
                              void* d_out, int out_size)
{
    const float* x    = (const float*)d_in[0];
    const float* W_mb = (const float*)d_in[1];
    const float* b_mb = (const float*)d_in[2];
    const float* a_mb = (const float*)d_in[3];
    const float* W_m  = (const float*)d_in[4];
    const float* b_m  = (const float*)d_in[5];
    const float* a_m  = (const float*)d_in[6];
    const float* W_a  = (const float*)d_in[7];
    const float* b_a  = (const float*)d_in[8];
    const float* a_a  = (const float*)d_in[9];
    float* out = (float*)d_out;

    float* p_mb;   cudaGetSymbolAddress((void**)&p_mb, g_mb);
    float* p_ref;  cudaGetSymbolAddress((void**)&p_ref, g_ref);
    float* p_mall; cudaGetSymbolAddress((void**)&p_mall, g_mall);
    float* p_ball; cudaGetSymbolAddress((void**)&p_ball, g_ball);
    float* p_sc;   cudaGetSymbolAddress((void**)&p_sc, g_sc);
    float* p_O;    cudaGetSymbolAddress((void**)&p_O, g_O);
    __nv_bfloat16* p_xqs;   cudaGetSymbolAddress((void**)&p_xqs, g_xqs);
    __nv_bfloat16* p_wns;   cudaGetSymbolAddress((void**)&p_wns, g_wns);
    __nv_bfloat16* p_attns; cudaGetSymbolAddress((void**)&p_attns, g_attns);
    __nv_bfloat16* p_rawTs; cudaGetSymbolAddress((void**)&p_rawTs, g_rawTs);

    cudaFuncSetAttribute(k_mma, cudaFuncAttributeMaxDynamicSharedMemorySize, MMA_SMEM);

    // 1) match_base
    k_conv1x1<<<dim3(9, NB * NCR), 256>>>(x, W_mb, b_mb, a_mb, p_mb, NCR, NP);
    // 2) pyramid bicubic resize
    k_resize<<<dim3(9, NB * NC, 5), 256>>>(x);
    // 3) keys / values images
    k_conv1x1<<<dim3(30, NB * NCR), 256>>>(p_ref, W_m, b_m, a_m, p_mall, NCR, STOT);
    k_conv1x1<<<dim3(30, NB * NC), 256>>>(p_ref, W_a, b_a, a_a, p_ball, NC, STOT);
    // 4) fp32 patch gathers
    k_xq<<<(NB * NP * KQ + 255) / 256, 256>>>();
    k_wn<<<(NB * LPAD * 32 + 255) / 256, 256>>>();
    // 5) bf16 split operand builds
    k_split_q<<<(NB * NP * KS1 + 255) / 256, 256>>>();
    k_split_wn<<<(NB * LPAD * KS1 + 255) / 256, 256>>>();
    k_rawTs<<<(NB * NV * LPAD + 255) / 256, 256>>>();
    // 6) scores = xq @ wn^T (3-term bf16 split, HMMA)
    k_mma<<<dim3(LPAD / 128, NP / 128, NB), 256, MMA_SMEM>>>(
        p_xqs, p_wns, p_sc, KP1 / 64, KP1, KP1, LPAD,
        (size_t)NP * KP1, (size_t)LPAD * KP1, (size_t)NP * LPAD);
    // 7) softmax + attn bf16 split (fused)
    k_softmax_split<<<(NB * NP * 32 + 255) / 256, 256>>>();
    // 8) O = attn @ rawT^T (3-term bf16 split, HMMA)
    k_mma<<<dim3(NV / 128, NP / 128, NB), 256, MMA_SMEM>>>(
        p_attns, p_rawTs, p_O, KP2 / 64, KP2, KP2, NV,
        (size_t)NP * KP2, (size_t)NV * KP2, (size_t)NP * NV);
    // 9) transposed-conv combine + residual
    k_epi<<<(NB * NC * NP + 255) / 256, 256>>>(x, out);
}